// round 15
// baseline (speedup 1.0000x reference)
#include <cuda_runtime.h>
#include <math.h>
#include <stdint.h>

#define NB   4
#define CM   128
#define CTOT 256
#define NO   128
#define NH   64
#define NW   64
#define NHW  4096
#define OFFC 54

// ---- packed f32x2 helpers (Blackwell FFMA2 path) ----
#define FFMA2(d, a, b) asm("fma.rn.f32x2 %0, %1, %2, %0;" : "+l"(d) : "l"(a), "l"(b))
__device__ __forceinline__ unsigned long long pack2b(float x) {
    unsigned long long r; asm("mov.b64 %0, {%1, %1};" : "=l"(r) : "f"(x)); return r;
}
__device__ __forceinline__ float2 unpack2(unsigned long long v) {
    float2 f; asm("mov.b64 {%0, %1}, %2;" : "=f"(f.x), "=f"(f.y) : "l"(v)); return f;
}

// -------- device scratch --------
__device__ float g_off  [NB*OFFC*NHW];
__device__ float g_offs [4*NB*OFFC*NHW];       // offconv quarter partials
__device__ float g_xT   [8*4096*128];          // NHWC input: [b*2+g][pos][c]
__device__ float g_wT   [2*9*128*128];         // dconv_w: [g][k][c][o]
__device__ float g_wT1  [CTOT*9*OFFC];         // off_w:   [ci][kk][co]
__device__ float g_wT2  [NO*9*NO];             // conv2_w: [ci][kk][co]
__device__ float g_out1 [NB*NO*NHW];
__device__ float g_out1s[4*NB*NO*NHW];         // deform partials (g x chalf)
__device__ float g_out2 [NB*NO*NHW];
__device__ float g_out2s[4*NB*NO*NHW];         // conv2 quarter partials
__device__ float g_scale1[NO], g_shift1[NO], g_scale2[NO], g_shift2[NO];

// -------- K0: merged weight transpose + NCHW->NHWC input transpose --------
__global__ __launch_bounds__(256) void k_prep(const float* __restrict__ dconv_w,
                                              const float* __restrict__ off_w,
                                              const float* __restrict__ conv2_w,
                                              const float* __restrict__ xv,
                                              const float* __restrict__ xi) {
    __shared__ float s[128][33];
    int tid = threadIdx.x;
    if (blockIdx.x < 2214) {
        int idx = blockIdx.x * 256 + tid;
        if (idx < 294912) {
            int o = idx & 127; int c = (idx >> 7) & 127; int gk = idx >> 14;
            int k = gk % 9; int g = gk / 9;
            g_wT[idx] = dconv_w[(o * 256 + g * 128 + c) * 9 + k];
        } else if (idx < 294912 + 124416) {
            int j = idx - 294912;
            int co = j % 54; int a = j / 54; int ci = a / 9; int kk = a % 9;
            g_wT1[j] = off_w[(co * 256 + ci) * 9 + kk];
        } else if (idx < 294912 + 124416 + 147456) {
            int j = idx - 419328;
            int co = j & 127; int a = j >> 7; int ci = a / 9; int kk = a % 9;
            g_wT2[j] = conv2_w[(co * 128 + ci) * 9 + kk];
        }
    } else {
        int bx = blockIdx.x - 2214;
        int bg = bx >> 7; int tile = bx & 127;
        int g = bg & 1; int b = bg >> 1;
        int pos0 = tile * 32;
        const float* src = (g ? xi : xv) + (size_t)b * 128 * NHW;
#pragma unroll
        for (int it = 0; it < 16; it++) {
            int i = tid + it * 256;
            int c = i >> 5; int p = i & 31;
            s[c][p] = src[(size_t)c * NHW + pos0 + p];
        }
        __syncthreads();
        float* dst = g_xT + ((size_t)bg * 4096 + pos0) * 128;
#pragma unroll
        for (int it = 0; it < 16; it++) {
            int j = tid + it * 256;
            int p = j >> 7; int c = j & 127;
            dst[(size_t)p * 128 + c] = s[c][p];
        }
    }
}

// -------- K1: offset conv3x3, quarter ci split, 2 h-rows per CTA. grid 512 --------
__global__ __launch_bounds__(256) void k_offconv(const float* __restrict__ xv,
                                                 const float* __restrict__ xi) {
    int quarter = blockIdx.x >> 7; int rem = blockIdx.x & 127;
    int b = rem >> 5; int hp = rem & 31; int h0 = hp * 2;
    int tid = threadIdx.x; int w = tid & 63; int q = tid >> 6;
    const float* xsrc = (quarter < 2) ? xv : xi;
    float* outbuf = g_offs + (size_t)quarter * (NB * OFFC * NHW);

    __shared__ float sx[16 * 4 * 66];
    __shared__ float sw[16 * 9 * 4 * 16];

    unsigned long long accp[2][8];
#pragma unroll
    for (int r = 0; r < 2; r++)
#pragma unroll
        for (int p = 0; p < 8; p++) accp[r][p] = 0ull;

    for (int ch = 0; ch < 4; ch++) {
        int ci0 = quarter * 64 + ch * 16;
        int cl0 = (quarter & 1) * 64 + ch * 16;
        __syncthreads();
        for (int i = tid; i < 16 * 9 * 4 * 2; i += 256) {
            int j = 14 + (i & 1); int aq = i >> 1;
            sw[aq * 16 + j] = 0.f;
        }
        for (int i = tid; i < 16 * 9 * 54; i += 256) {
            int a = i / 54; int co = i - a * 54;
            sw[(a * 4 + (co & 3)) * 16 + (co >> 2)] = g_wT1[ci0 * (9 * 54) + i];
        }
        for (int i = tid; i < 16 * 4 * 66; i += 256) {
            int ci = i / 264; int r2 = i - ci * 264; int r = r2 / 66; int wc = r2 - r * 66;
            int hh = h0 - 1 + r; int ww = wc - 1;
            float v = 0.f;
            if (hh >= 0 && hh < 64 && ww >= 0 && ww < 64)
                v = xsrc[((size_t)(b * 128 + cl0 + ci) * 64 + hh) * 64 + ww];
            sx[i] = v;
        }
        __syncthreads();

        for (int ci = 0; ci < 16; ci++) {
#pragma unroll
            for (int kk = 0; kk < 9; kk++) {
                int kx = kk % 3, ky = kk / 3;
                float x0 = sx[ci * 264 + ky * 66 + w + kx];
                float x1 = sx[ci * 264 + (ky + 1) * 66 + w + kx];
                unsigned long long xb0 = pack2b(x0);
                unsigned long long xb1 = pack2b(x1);
                const ulonglong2* wrow = (const ulonglong2*)&sw[((ci * 9 + kk) * 4 + q) * 16];
#pragma unroll
                for (int j4 = 0; j4 < 4; j4++) {
                    ulonglong2 wv = wrow[j4];
                    FFMA2(accp[0][2 * j4],     wv.x, xb0);
                    FFMA2(accp[0][2 * j4 + 1], wv.y, xb0);
                    FFMA2(accp[1][2 * j4],     wv.x, xb1);
                    FFMA2(accp[1][2 * j4 + 1], wv.y, xb1);
                }
            }
        }
    }

#pragma unroll
    for (int r = 0; r < 2; r++) {
        int h = h0 + r;
#pragma unroll
        for (int p = 0; p < 8; p++) {
            float2 f2 = unpack2(accp[r][p]);
            int j0 = (p >> 1) * 4 + (p & 1) * 2;
#pragma unroll
            for (int s = 0; s < 2; s++) {
                int co = q + 4 * (j0 + s);
                if (co < 54)
                    outbuf[((size_t)(b * 54 + co) * 64 + h) * 64 + w] = (s == 0 ? f2.x : f2.y);
            }
        }
    }
}

// -------- K1b: combine 4 quarters + bias + sigmoid --------
__global__ void k_offpost(const float* __restrict__ off_b) {
    const int N = NB * OFFC * NHW;
    int idx = blockIdx.x * 256 + threadIdx.x;
    int co = (idx >> 12) % 54;
    float v = g_offs[idx] + g_offs[N + idx] + g_offs[2 * N + idx] + g_offs[3 * N + idx]
            + off_b[co];
    if (co >= 36) v = 1.f / (1.f + expf(-v));
    g_off[idx] = v;
}

// -------- K2: deform-sample + grouped GEMM, register-pipelined gathers. grid 1024 --------
// Per-thread prefetch of next chunk's 4-corner gather overlaps current chunk's MMA.
// Weights read directly from g_wT via __ldg (L1-hot 16KB slab) — no smem staging.
__global__ __launch_bounds__(256, 2) void k_deform() {
    int bx = blockIdx.x;
    int ch2 = bx >> 9;              // c-half
    int g   = (bx >> 8) & 1;
    int b   = (bx >> 6) & 3;
    int h   = bx & 63;
    int tid = threadIdx.x;
    int og = tid >> 4; int pw = tid & 15;
    float* outbuf = g_out1s + (size_t)(g * 2 + ch2) * (NB * NO * NHW);
    const float4* xT4 = (const float4*)g_xT + (size_t)(b * 2 + g) * 4096 * 32;
    const float* offbase = g_off + (size_t)b * 54 * NHW + h * 64;
    const ulonglong2* wbase = (const ulonglong2*)g_wT;   // [gk*128+c][128o] rows = 32 ull2

    __shared__ float sv[2][2048];      // [buf][32 c][64 px]
    __shared__ int   si[2][4][64];     // [parity][corner][px]
    __shared__ float sb[2][4][64];

    auto compute_offsets = [&](int k, int par) {
        int corner = tid >> 6;
        int w = tid & 63;
        int ky = k / 3 - 1, kx = (k % 3) - 1;
        const float* offp = offbase + w;
        float dy = offp[(size_t)(g * 18 + 2 * k) * NHW];
        float dx = offp[(size_t)(g * 18 + 2 * k + 1) * NHW];
        float m  = offp[(size_t)(36 + g * 9 + k) * NHW];
        float py = dy + (float)(h + ky);
        float px = dx + (float)(w + kx);
        float fy = floorf(py), fx = floorf(px);
        float ly = py - fy,   lx = px - fx;
        int y0 = (int)fy, x0 = (int)fx;
        int yc = (corner & 2) ? y0 + 1 : y0;
        int xc = (corner & 1) ? x0 + 1 : x0;
        float ok = (yc >= 0 && yc < 64 && xc >= 0 && xc < 64) ? 1.f : 0.f;
        float wy = (corner & 2) ? ly : 1.f - ly;
        float wx = (corner & 1) ? lx : 1.f - lx;
        int cy = min(max(yc, 0), 63), cx = min(max(xc, 0), 63);
        si[par][corner][w] = cy * 64 + cx;
        sb[par][corner][w] = wy * wx * ok * m;
    };

    float4 G[2][4];                    // prefetched gather data: [task][corner]
    int myc4 = tid >> 6;               // task 0 c4 (0..3); task 1 adds 4
    int mypx = tid & 63;

    auto issue_gather = [&](int cnt) {
        int k = cnt >> 1; int cc = cnt & 1; int par = k & 1;
        int c0 = ch2 * 64 + cc * 32;
        int i0 = si[par][0][mypx], i1 = si[par][1][mypx];
        int i2 = si[par][2][mypx], i3 = si[par][3][mypx];
#pragma unroll
        for (int t = 0; t < 2; t++) {
            const float4* bp = xT4 + (c0 >> 2) + myc4 + t * 4;
            G[t][0] = __ldg(bp + i0 * 32);
            G[t][1] = __ldg(bp + i1 * 32);
            G[t][2] = __ldg(bp + i2 * 32);
            G[t][3] = __ldg(bp + i3 * 32);
        }
    };

    unsigned long long accp[4][4];
#pragma unroll
    for (int op = 0; op < 4; op++)
#pragma unroll
        for (int pi = 0; pi < 4; pi++) accp[op][pi] = 0ull;

    compute_offsets(0, 0);
    __syncthreads();
    issue_gather(0);

    for (int cnt = 0; cnt < 18; cnt++) {
        int k = cnt >> 1; int cc = cnt & 1; int buf = cnt & 1; int par = k & 1;
        // combine prefetched data with bilinear weights -> STS into sv[buf]
        {
            float b0 = sb[par][0][mypx], b1 = sb[par][1][mypx];
            float b2 = sb[par][2][mypx], b3 = sb[par][3][mypx];
            float* svb = sv[buf];
#pragma unroll
            for (int t = 0; t < 2; t++) {
                float* svp = svb + (myc4 + t * 4) * 256 + mypx;
                svp[0]   = b0 * G[t][0].x + b1 * G[t][1].x + b2 * G[t][2].x + b3 * G[t][3].x;
                svp[64]  = b0 * G[t][0].y + b1 * G[t][1].y + b2 * G[t][2].y + b3 * G[t][3].y;
                svp[128] = b0 * G[t][0].z + b1 * G[t][1].z + b2 * G[t][2].z + b3 * G[t][3].z;
                svp[192] = b0 * G[t][0].w + b1 * G[t][1].w + b2 * G[t][2].w + b3 * G[t][3].w;
            }
        }
        if (cc == 1 && k < 8) compute_offsets(k + 1, par ^ 1);
        __syncthreads();
        if (cnt < 17) issue_gather(cnt + 1);     // latency hidden under MMA below
        // MMA: weights via __ldg, sv from smem
        {
            int c0 = ch2 * 64 + cc * 32;
            const ulonglong2* wp = wbase + ((size_t)(g * 9 + k) * 128 + c0) * 32 + og * 2;
            const float* svb = sv[buf];
#pragma unroll
            for (int c = 0; c < 32; c++) {
                float4 xa = *(const float4*)&svb[c * 64 + pw * 4];
                unsigned long long xp0 = pack2b(xa.x), xp1 = pack2b(xa.y);
                unsigned long long xp2 = pack2b(xa.z), xp3 = pack2b(xa.w);
                ulonglong2 wv0 = __ldg(wp + c * 32);
                ulonglong2 wv1 = __ldg(wp + c * 32 + 1);
                FFMA2(accp[0][0], wv0.x, xp0); FFMA2(accp[0][1], wv0.x, xp1);
                FFMA2(accp[0][2], wv0.x, xp2); FFMA2(accp[0][3], wv0.x, xp3);
                FFMA2(accp[1][0], wv0.y, xp0); FFMA2(accp[1][1], wv0.y, xp1);
                FFMA2(accp[1][2], wv0.y, xp2); FFMA2(accp[1][3], wv0.y, xp3);
                FFMA2(accp[2][0], wv1.x, xp0); FFMA2(accp[2][1], wv1.x, xp1);
                FFMA2(accp[2][2], wv1.x, xp2); FFMA2(accp[2][3], wv1.x, xp3);
                FFMA2(accp[3][0], wv1.y, xp0); FFMA2(accp[3][1], wv1.y, xp1);
                FFMA2(accp[3][2], wv1.y, xp2); FFMA2(accp[3][3], wv1.y, xp3);
            }
        }
    }

    // epilogue: float4 stores
    float* outp = outbuf + ((size_t)(b * 128) * 64 + h) * 64;
#pragma unroll
    for (int op = 0; op < 4; op++) {
        float2 a0 = unpack2(accp[op][0]);
        float2 a1 = unpack2(accp[op][1]);
        float2 a2 = unpack2(accp[op][2]);
        float2 a3 = unpack2(accp[op][3]);
        int o0 = og * 8 + 2 * op;
        *(float4*)(outp + (size_t)o0 * NHW + pw * 4)       = make_float4(a0.x, a1.x, a2.x, a3.x);
        *(float4*)(outp + (size_t)(o0 + 1) * NHW + pw * 4) = make_float4(a0.y, a1.y, a2.y, a3.y);
    }
}

// -------- K3: combine 4 deform partials + BN1 stats + fold --------
__global__ __launch_bounds__(256) void k_bn1(const float* __restrict__ gamma,
                                             const float* __restrict__ beta) {
    const size_t N = (size_t)NB * NO * NHW;
    int c = blockIdx.x; int tid = threadIdx.x;
    __shared__ float ssum[256], ssq[256];
    float s = 0.f, sq = 0.f;
    for (int b = 0; b < NB; b++) {
        size_t base = (size_t)(b * 128 + c) * NHW;
        const float4* p0 = (const float4*)(g_out1s + base);
        const float4* p1 = (const float4*)(g_out1s + N + base);
        const float4* p2 = (const float4*)(g_out1s + 2 * N + base);
        const float4* p3 = (const float4*)(g_out1s + 3 * N + base);
        float4* po = (float4*)(g_out1 + base);
        for (int i = tid; i < 1024; i += 256) {
            float4 a = p0[i], bq = p1[i], cq = p2[i], dq = p3[i];
            float4 v = make_float4(a.x + bq.x + cq.x + dq.x, a.y + bq.y + cq.y + dq.y,
                                   a.z + bq.z + cq.z + dq.z, a.w + bq.w + cq.w + dq.w);
            po[i] = v;
            s  += v.x + v.y + v.z + v.w;
            sq += v.x * v.x + v.y * v.y + v.z * v.z + v.w * v.w;
        }
    }
    ssum[tid] = s; ssq[tid] = sq;
    __syncthreads();
    for (int st = 128; st; st >>= 1) {
        if (tid < st) { ssum[tid] += ssum[tid + st]; ssq[tid] += ssq[tid + st]; }
        __syncthreads();
    }
    if (tid == 0) {
        float m  = ssum[0] * (1.f / 16384.f);
        float vv = ssq[0]  * (1.f / 16384.f) - m * m;
        float sc = gamma[c] * rsqrtf(vv + 1e-5f);
        g_scale1[c] = sc;
        g_shift1[c] = beta[c] - m * sc;
    }
}

// -------- K4: conv3x3 (128->128), BN1+ReLU at load, quarter ci x co-half x h-pair. grid 1024 --------
__global__ __launch_bounds__(256) void k_conv2() {
    int quarter = blockIdx.x >> 8;
    int rem = blockIdx.x & 255;
    int cohalf = rem >> 7;
    int rem2 = rem & 127;
    int b = rem2 >> 5; int hp = rem2 & 31; int h0 = hp * 2;
    int tid = threadIdx.x; int w = tid & 63; int q = tid >> 6;
    float* outbuf = g_out2s + (size_t)quarter * (NB * NO * NHW);
    int co_base = cohalf * 64 + q * 16;

    __shared__ float sx[8 * 4 * 66];
    __shared__ float sw[8 * 9 * 64];

    unsigned long long accp[2][8];
#pragma unroll
    for (int r = 0; r < 2; r++)
#pragma unroll
        for (int p = 0; p < 8; p++) accp[r][p] = 0ull;

    for (int ch = 0; ch < 4; ch++) {
        int ci0 = quarter * 32 + ch * 8;
        __syncthreads();
        float4* sw4 = (float4*)sw;
        for (int i = tid; i < 1152; i += 256) {
            int a = i >> 4; int j = i & 15;
            sw4[i] = *(const float4*)(g_wT2 + (size_t)(ci0 * 9 + a) * 128 + cohalf * 64 + j * 4);
        }
        for (int i = tid; i < 8 * 4 * 66; i += 256) {
            int ci = i / 264; int r2 = i - ci * 264; int r = r2 / 66; int wc = r2 - r * 66;
            int hh = h0 - 1 + r; int ww = wc - 1; int c = ci0 + ci;
            float v = 0.f;
            if (hh >= 0 && hh < 64 && ww >= 0 && ww < 64) {
                float raw = g_out1[((size_t)(b * 128 + c) * 64 + hh) * 64 + ww];
                v = fmaxf(0.f, raw * g_scale1[c] + g_shift1[c]);
            }
            sx[i] = v;
        }
        __syncthreads();

        for (int ci = 0; ci < 8; ci++) {
#pragma unroll
            for (int kk = 0; kk < 9; kk++) {
                int ky = kk / 3, kx = kk % 3;
                float x0 = sx[ci * 264 + ky * 66 + w + kx];
                float x1 = sx[ci * 264 + (ky + 1) * 66 + w + kx];
                unsigned long long xb0 = pack2b(x0);
                unsigned long long xb1 = pack2b(x1);
                const ulonglong2* wrow = (const ulonglong2*)&sw[(ci * 9 + kk) * 64 + q * 16];
#pragma unroll
                for (int j4 = 0; j4 < 4; j4++) {
                    ulonglong2 wv = wrow[j4];
                    FFMA2(accp[0][2 * j4],     wv.x, xb0);
                    FFMA2(accp[0][2 * j4 + 1], wv.y, xb0);
                    FFMA2(accp[1][2 * j4],     wv.x, xb1);
                    FFMA2(accp[1][2 * j4 + 1], wv.y, xb1);
                }
            }
        }
    }

#pragma unroll
    for (int r = 0; r < 2; r++) {
        int h = h0 + r;
#pragma unroll
        for (int p = 0; p < 8; p++) {
            float2 f2 = unpack2(accp[r][p]);
            int co = co_base + 2 * p;
            outbuf[((size_t)(b * 128 + co) * 64 + h) * 64 + w]     = f2.x;
            outbuf[((size_t)(b * 128 + co + 1) * 64 + h) * 64 + w] = f2.y;
        }
    }
}

// -------- K5: combine 4 conv2 partials + BN2 stats + fold --------
__global__ __launch_bounds__(256) void k_bn2(const float* __restrict__ gamma,
                                             const float* __restrict__ beta) {
    const size_t N = (size_t)NB * NO * NHW;
    int c = blockIdx.x; int tid = threadIdx.x;
    __shared__ float ssum[256], ssq[256];
    float s = 0.f, sq = 0.f;
    for (int b = 0; b < NB; b++) {
        size_t base = (size_t)(b * 128 + c) * NHW;
        const float4* p0 = (const float4*)(g_out2s + base);
        const float4* p1 = (const float4*)(g_out2s + N + base);
        const float4* p2 = (const float4*)(g_out2s + 2 * N + base);
        const float4* p3 = (const float4*)(g_out2s + 3 * N + base);
        float4* po = (float4*)(g_out2 + base);
        for (int i = tid; i < 1024; i += 256) {
            float4 a = p0[i], bq = p1[i], cq = p2[i], dq = p3[i];
            float4 v = make_float4(a.x + bq.x + cq.x + dq.x, a.y + bq.y + cq.y + dq.y,
                                   a.z + bq.z + cq.z + dq.z, a.w + bq.w + cq.w + dq.w);
            po[i] = v;
            s  += v.x + v.y + v.z + v.w;
            sq += v.x * v.x + v.y * v.y + v.z * v.z + v.w * v.w;
        }
    }
    ssum[tid] = s; ssq[tid] = sq;
    __syncthreads();
    for (int st = 128; st; st >>= 1) {
        if (tid < st) { ssum[tid] += ssum[tid + st]; ssq[tid] += ssq[tid + st]; }
        __syncthreads();
    }
    if (tid == 0) {
        float m  = ssum[0] * (1.f / 16384.f);
        float vv = ssq[0]  * (1.f / 16384.f) - m * m;
        float sc = gamma[c] * rsqrtf(vv + 1e-5f);
        g_scale2[c] = sc;
        g_shift2[c] = beta[c] - m * sc;
    }
}

// -------- K6: final BN2 + ReLU elementwise into d_out --------
__global__ void k_final(float* __restrict__ out) {
    int idx = blockIdx.x * 256 + threadIdx.x;
    const float4* in4 = (const float4*)g_out2;
    float4 v = in4[idx];
    int c = (idx >> 10) & 127;
    float sc = g_scale2[c], sh = g_shift2[c];
    float4 r;
    r.x = fmaxf(0.f, v.x * sc + sh);
    r.y = fmaxf(0.f, v.y * sc + sh);
    r.z = fmaxf(0.f, v.z * sc + sh);
    r.w = fmaxf(0.f, v.w * sc + sh);
    ((float4*)out)[idx] = r;
}

// -------- host launcher (graph-capturable) --------
extern "C" void kernel_launch(void* const* d_in, const int* in_sizes, int n_in,
                              void* d_out, int out_size) {
    const float* input_v = (const float*)d_in[0];
    const float* input_i = (const float*)d_in[1];
    const float* off_w   = (const float*)d_in[2];
    const float* off_b   = (const float*)d_in[3];
    const float* dconv_w = (const float*)d_in[4];
    const float* bn1_g   = (const float*)d_in[5];
    const float* bn1_b   = (const float*)d_in[6];
    const float* conv2_w = (const float*)d_in[7];
    const float* bn2_g   = (const float*)d_in[8];
    const float* bn2_b   = (const float*)d_in[9];
    float* out = (float*)d_out;

    k_prep<<<3238, 256>>>(dconv_w, off_w, conv2_w, input_v, input_i);
    k_offconv<<<512, 256>>>(input_v, input_i);
    k_offpost<<<3456, 256>>>(off_b);
    k_deform<<<1024, 256>>>();
    k_bn1<<<128, 256>>>(bn1_g, bn1_b);
    k_conv2<<<1024, 256>>>();
    k_bn2<<<128, 256>>>(bn2_g, bn2_b);
    k_final<<<2048, 256>>>(out);
}

// round 16
// speedup vs baseline: 1.3618x; 1.3618x over previous
#include <cuda_runtime.h>
#include <math.h>
#include <stdint.h>

#define NB   4
#define CM   128
#define CTOT 256
#define NO   128
#define NH   64
#define NW   64
#define NHW  4096
#define OFFC 54

// ---- packed f32x2 helpers (Blackwell FFMA2 path) ----
#define FFMA2(d, a, b) asm("fma.rn.f32x2 %0, %1, %2, %0;" : "+l"(d) : "l"(a), "l"(b))
__device__ __forceinline__ unsigned long long pack2b(float x) {
    unsigned long long r; asm("mov.b64 %0, {%1, %1};" : "=l"(r) : "f"(x)); return r;
}
__device__ __forceinline__ float2 unpack2(unsigned long long v) {
    float2 f; asm("mov.b64 {%0, %1}, %2;" : "=f"(f.x), "=f"(f.y) : "l"(v)); return f;
}

// -------- device scratch --------
__device__ float g_off  [NB*OFFC*NHW];
__device__ float g_offs [4*NB*OFFC*NHW];       // offconv quarter partials
__device__ float g_xT   [8*4096*128];          // NHWC input: [b*2+g][pos][c]
__device__ float g_wT   [2*9*128*128];         // dconv_w: [g][k][c][o]
__device__ float g_wT1  [CTOT*9*OFFC];         // off_w:   [ci][kk][co]
__device__ float g_wT2  [NO*9*NO];             // conv2_w: [ci][kk][co]
__device__ float g_out1 [NB*NO*NHW];
__device__ float g_out1s[4*NB*NO*NHW];         // deform partials (g x chalf)
__device__ float g_out2 [NB*NO*NHW];
__device__ float g_out2s[4*NB*NO*NHW];         // conv2 quarter partials
__device__ float g_scale1[NO], g_shift1[NO], g_scale2[NO], g_shift2[NO];

// -------- K0: merged weight transpose + NCHW->NHWC input transpose --------
__global__ __launch_bounds__(256) void k_prep(const float* __restrict__ dconv_w,
                                              const float* __restrict__ off_w,
                                              const float* __restrict__ conv2_w,
                                              const float* __restrict__ xv,
                                              const float* __restrict__ xi) {
    __shared__ float s[128][33];
    int tid = threadIdx.x;
    if (blockIdx.x < 2214) {
        int idx = blockIdx.x * 256 + tid;
        if (idx < 294912) {
            int o = idx & 127; int c = (idx >> 7) & 127; int gk = idx >> 14;
            int k = gk % 9; int g = gk / 9;
            g_wT[idx] = dconv_w[(o * 256 + g * 128 + c) * 9 + k];
        } else if (idx < 294912 + 124416) {
            int j = idx - 294912;
            int co = j % 54; int a = j / 54; int ci = a / 9; int kk = a % 9;
            g_wT1[j] = off_w[(co * 256 + ci) * 9 + kk];
        } else if (idx < 294912 + 124416 + 147456) {
            int j = idx - 419328;
            int co = j & 127; int a = j >> 7; int ci = a / 9; int kk = a % 9;
            g_wT2[j] = conv2_w[(co * 128 + ci) * 9 + kk];
        }
    } else {
        int bx = blockIdx.x - 2214;
        int bg = bx >> 7; int tile = bx & 127;
        int g = bg & 1; int b = bg >> 1;
        int pos0 = tile * 32;
        const float* src = (g ? xi : xv) + (size_t)b * 128 * NHW;
#pragma unroll
        for (int it = 0; it < 16; it++) {
            int i = tid + it * 256;
            int c = i >> 5; int p = i & 31;
            s[c][p] = src[(size_t)c * NHW + pos0 + p];
        }
        __syncthreads();
        float* dst = g_xT + ((size_t)bg * 4096 + pos0) * 128;
#pragma unroll
        for (int it = 0; it < 16; it++) {
            int j = tid + it * 256;
            int p = j >> 7; int c = j & 127;
            dst[(size_t)p * 128 + c] = s[c][p];
        }
    }
}

// -------- K1: offset conv3x3, quarter ci split, 2 h-rows per CTA. grid 512 --------
__global__ __launch_bounds__(256) void k_offconv(const float* __restrict__ xv,
                                                 const float* __restrict__ xi) {
    int quarter = blockIdx.x >> 7; int rem = blockIdx.x & 127;
    int b = rem >> 5; int hp = rem & 31; int h0 = hp * 2;
    int tid = threadIdx.x; int w = tid & 63; int q = tid >> 6;
    const float* xsrc = (quarter < 2) ? xv : xi;
    float* outbuf = g_offs + (size_t)quarter * (NB * OFFC * NHW);

    __shared__ float sx[16 * 4 * 66];
    __shared__ float sw[16 * 9 * 4 * 16];

    unsigned long long accp[2][8];
#pragma unroll
    for (int r = 0; r < 2; r++)
#pragma unroll
        for (int p = 0; p < 8; p++) accp[r][p] = 0ull;

    for (int ch = 0; ch < 4; ch++) {
        int ci0 = quarter * 64 + ch * 16;
        int cl0 = (quarter & 1) * 64 + ch * 16;
        __syncthreads();
        for (int i = tid; i < 16 * 9 * 4 * 2; i += 256) {
            int j = 14 + (i & 1); int aq = i >> 1;
            sw[aq * 16 + j] = 0.f;
        }
        for (int i = tid; i < 16 * 9 * 54; i += 256) {
            int a = i / 54; int co = i - a * 54;
            sw[(a * 4 + (co & 3)) * 16 + (co >> 2)] = g_wT1[ci0 * (9 * 54) + i];
        }
        for (int i = tid; i < 16 * 4 * 66; i += 256) {
            int ci = i / 264; int r2 = i - ci * 264; int r = r2 / 66; int wc = r2 - r * 66;
            int hh = h0 - 1 + r; int ww = wc - 1;
            float v = 0.f;
            if (hh >= 0 && hh < 64 && ww >= 0 && ww < 64)
                v = xsrc[((size_t)(b * 128 + cl0 + ci) * 64 + hh) * 64 + ww];
            sx[i] = v;
        }
        __syncthreads();

        for (int ci = 0; ci < 16; ci++) {
#pragma unroll
            for (int kk = 0; kk < 9; kk++) {
                int kx = kk % 3, ky = kk / 3;
                float x0 = sx[ci * 264 + ky * 66 + w + kx];
                float x1 = sx[ci * 264 + (ky + 1) * 66 + w + kx];
                unsigned long long xb0 = pack2b(x0);
                unsigned long long xb1 = pack2b(x1);
                const ulonglong2* wrow = (const ulonglong2*)&sw[((ci * 9 + kk) * 4 + q) * 16];
#pragma unroll
                for (int j4 = 0; j4 < 4; j4++) {
                    ulonglong2 wv = wrow[j4];
                    FFMA2(accp[0][2 * j4],     wv.x, xb0);
                    FFMA2(accp[0][2 * j4 + 1], wv.y, xb0);
                    FFMA2(accp[1][2 * j4],     wv.x, xb1);
                    FFMA2(accp[1][2 * j4 + 1], wv.y, xb1);
                }
            }
        }
    }

#pragma unroll
    for (int r = 0; r < 2; r++) {
        int h = h0 + r;
#pragma unroll
        for (int p = 0; p < 8; p++) {
            float2 f2 = unpack2(accp[r][p]);
            int j0 = (p >> 1) * 4 + (p & 1) * 2;
#pragma unroll
            for (int s = 0; s < 2; s++) {
                int co = q + 4 * (j0 + s);
                if (co < 54)
                    outbuf[((size_t)(b * 54 + co) * 64 + h) * 64 + w] = (s == 0 ? f2.x : f2.y);
            }
        }
    }
}

// -------- K1b: combine 4 quarters + bias + sigmoid --------
__global__ void k_offpost(const float* __restrict__ off_b) {
    const int N = NB * OFFC * NHW;
    int idx = blockIdx.x * 256 + threadIdx.x;
    int co = (idx >> 12) % 54;
    float v = g_offs[idx] + g_offs[N + idx] + g_offs[2 * N + idx] + g_offs[3 * N + idx]
            + off_b[co];
    if (co >= 36) v = 1.f / (1.f + expf(-v));
    g_off[idx] = v;
}

// -------- K2: deform-sample + grouped GEMM, split by (g, c-half). grid 1024 --------
// R12 structure (smem weights, ping-pong offsets, 64 regs) with COALESCED gather
// mapping: warp lanes cover consecutive c4 for shared px -> 4 L1 wavefronts/LDG
// instead of 32. sv rows padded to 68 floats to cap STS conflicts at 4-way.
#define SVP 68
__global__ __launch_bounds__(256) void k_deform() {
    int bx = blockIdx.x;
    int ch2 = bx >> 9;              // c-half
    int g   = (bx >> 8) & 1;
    int b   = (bx >> 6) & 3;
    int h   = bx & 63;
    int tid = threadIdx.x;
    int og = tid >> 4; int pw = tid & 15;
    float* outbuf = g_out1s + (size_t)(g * 2 + ch2) * (NB * NO * NHW);
    const float4* xT4 = (const float4*)g_xT + (size_t)(b * 2 + g) * 4096 * 32;
    const float* offbase = g_off + (size_t)b * 54 * NHW + h * 64;

    __shared__ float sv [2][32 * SVP];   // [buf][32 c][68 px-padded]
    __shared__ float swt[2][4096];       // [buf][32 c][128 o]
    __shared__ int   si[2][4][64];       // [parity][corner][px]
    __shared__ float sb[2][4][64];

    auto compute_offsets = [&](int k, int par) {
        int corner = tid >> 6;
        int w = tid & 63;
        int ky = k / 3 - 1, kx = (k % 3) - 1;
        const float* offp = offbase + w;
        float dy = offp[(size_t)(g * 18 + 2 * k) * NHW];
        float dx = offp[(size_t)(g * 18 + 2 * k + 1) * NHW];
        float m  = offp[(size_t)(36 + g * 9 + k) * NHW];
        float py = dy + (float)(h + ky);
        float px = dx + (float)(w + kx);
        float fy = floorf(py), fx = floorf(px);
        float ly = py - fy,   lx = px - fx;
        int y0 = (int)fy, x0 = (int)fx;
        int yc = (corner & 2) ? y0 + 1 : y0;
        int xc = (corner & 1) ? x0 + 1 : x0;
        float ok = (yc >= 0 && yc < 64 && xc >= 0 && xc < 64) ? 1.f : 0.f;
        float wy = (corner & 2) ? ly : 1.f - ly;
        float wx = (corner & 1) ? lx : 1.f - lx;
        int cy = min(max(yc, 0), 63), cx = min(max(xc, 0), 63);
        si[par][corner][w] = cy * 64 + cx;
        sb[par][corner][w] = wy * wx * ok * m;
    };

    unsigned long long accp[4][4];
#pragma unroll
    for (int op = 0; op < 4; op++)
#pragma unroll
        for (int pi = 0; pi < 4; pi++) accp[op][pi] = 0ull;

    compute_offsets(0, 0);
    __syncthreads();

    for (int cnt = 0; cnt < 18; cnt++) {
        int k = cnt >> 1; int cc = cnt & 1; int buf = cnt & 1; int par = k & 1;
        int c0 = ch2 * 64 + cc * 32;
        // stage weights [32 c][128 o] via float4 (coalesced)
        const float4* wp4 = (const float4*)(g_wT + ((size_t)(g * 9 + k) * 128 + c0) * 128);
        float4* swb4 = (float4*)swt[buf];
#pragma unroll
        for (int i = 0; i < 4; i++) swb4[tid + i * 256] = wp4[tid + i * 256];
        // gather: COALESCED mapping — c4 in low lane bits, px shared per 8 lanes
        float* svb = sv[buf];
#pragma unroll
        for (int t = 0; t < 2; t++) {
            int lin = tid + t * 256;        // 512 tasks
            int c4 = lin & 7;               // consecutive float4 per lane group
            int px = lin >> 3;              // 0..63
            const float4* bp = xT4 + (c0 >> 2) + c4;
            float4 q0 = __ldg(bp + si[par][0][px] * 32);
            float4 q1 = __ldg(bp + si[par][1][px] * 32);
            float4 q2 = __ldg(bp + si[par][2][px] * 32);
            float4 q3 = __ldg(bp + si[par][3][px] * 32);
            float b0 = sb[par][0][px], b1 = sb[par][1][px];
            float b2 = sb[par][2][px], b3 = sb[par][3][px];
            float* svp = svb + (c4 * 4) * SVP + px;
            svp[0]       = b0 * q0.x + b1 * q1.x + b2 * q2.x + b3 * q3.x;
            svp[SVP]     = b0 * q0.y + b1 * q1.y + b2 * q2.y + b3 * q3.y;
            svp[2 * SVP] = b0 * q0.z + b1 * q1.z + b2 * q2.z + b3 * q3.z;
            svp[3 * SVP] = b0 * q0.w + b1 * q1.w + b2 * q2.w + b3 * q3.w;
        }
        if (cc == 1 && k < 8) compute_offsets(k + 1, par ^ 1);
        __syncthreads();
        float* swb = swt[buf];
        float* svb2 = sv[buf];
#pragma unroll
        for (int c = 0; c < 32; c++) {
            float4 xa = *(const float4*)&svb2[c * SVP + pw * 4];
            unsigned long long xp0 = pack2b(xa.x), xp1 = pack2b(xa.y);
            unsigned long long xp2 = pack2b(xa.z), xp3 = pack2b(xa.w);
            ulonglong2 wv0 = *(const ulonglong2*)&swb[c * 128 + og * 8];
            ulonglong2 wv1 = *(const ulonglong2*)&swb[c * 128 + og * 8 + 4];
            FFMA2(accp[0][0], wv0.x, xp0); FFMA2(accp[0][1], wv0.x, xp1);
            FFMA2(accp[0][2], wv0.x, xp2); FFMA2(accp[0][3], wv0.x, xp3);
            FFMA2(accp[1][0], wv0.y, xp0); FFMA2(accp[1][1], wv0.y, xp1);
            FFMA2(accp[1][2], wv0.y, xp2); FFMA2(accp[1][3], wv0.y, xp3);
            FFMA2(accp[2][0], wv1.x, xp0); FFMA2(accp[2][1], wv1.x, xp1);
            FFMA2(accp[2][2], wv1.x, xp2); FFMA2(accp[2][3], wv1.x, xp3);
            FFMA2(accp[3][0], wv1.y, xp0); FFMA2(accp[3][1], wv1.y, xp1);
            FFMA2(accp[3][2], wv1.y, xp2); FFMA2(accp[3][3], wv1.y, xp3);
        }
    }

    // epilogue: float4 stores
    float* outp = outbuf + ((size_t)(b * 128) * 64 + h) * 64;
#pragma unroll
    for (int op = 0; op < 4; op++) {
        float2 a0 = unpack2(accp[op][0]);
        float2 a1 = unpack2(accp[op][1]);
        float2 a2 = unpack2(accp[op][2]);
        float2 a3 = unpack2(accp[op][3]);
        int o0 = og * 8 + 2 * op;
        *(float4*)(outp + (size_t)o0 * NHW + pw * 4)       = make_float4(a0.x, a1.x, a2.x, a3.x);
        *(float4*)(outp + (size_t)(o0 + 1) * NHW + pw * 4) = make_float4(a0.y, a1.y, a2.y, a3.y);
    }
}

// -------- K3: combine 4 deform partials + BN1 stats + fold --------
__global__ __launch_bounds__(256) void k_bn1(const float* __restrict__ gamma,
                                             const float* __restrict__ beta) {
    const size_t N = (size_t)NB * NO * NHW;
    int c = blockIdx.x; int tid = threadIdx.x;
    __shared__ float ssum[256], ssq[256];
    float s = 0.f, sq = 0.f;
    for (int b = 0; b < NB; b++) {
        size_t base = (size_t)(b * 128 + c) * NHW;
        const float4* p0 = (const float4*)(g_out1s + base);
        const float4* p1 = (const float4*)(g_out1s + N + base);
        const float4* p2 = (const float4*)(g_out1s + 2 * N + base);
        const float4* p3 = (const float4*)(g_out1s + 3 * N + base);
        float4* po = (float4*)(g_out1 + base);
        for (int i = tid; i < 1024; i += 256) {
            float4 a = p0[i], bq = p1[i], cq = p2[i], dq = p3[i];
            float4 v = make_float4(a.x + bq.x + cq.x + dq.x, a.y + bq.y + cq.y + dq.y,
                                   a.z + bq.z + cq.z + dq.z, a.w + bq.w + cq.w + dq.w);
            po[i] = v;
            s  += v.x + v.y + v.z + v.w;
            sq += v.x * v.x + v.y * v.y + v.z * v.z + v.w * v.w;
        }
    }
    ssum[tid] = s; ssq[tid] = sq;
    __syncthreads();
    for (int st = 128; st; st >>= 1) {
        if (tid < st) { ssum[tid] += ssum[tid + st]; ssq[tid] += ssq[tid + st]; }
        __syncthreads();
    }
    if (tid == 0) {
        float m  = ssum[0] * (1.f / 16384.f);
        float vv = ssq[0]  * (1.f / 16384.f) - m * m;
        float sc = gamma[c] * rsqrtf(vv + 1e-5f);
        g_scale1[c] = sc;
        g_shift1[c] = beta[c] - m * sc;
    }
}

// -------- K4: conv3x3 (128->128), BN1+ReLU at load, quarter ci x co-half x h-pair. grid 1024 --------
__global__ __launch_bounds__(256) void k_conv2() {
    int quarter = blockIdx.x >> 8;
    int rem = blockIdx.x & 255;
    int cohalf = rem >> 7;
    int rem2 = rem & 127;
    int b = rem2 >> 5; int hp = rem2 & 31; int h0 = hp * 2;
    int tid = threadIdx.x; int w = tid & 63; int q = tid >> 6;
    float* outbuf = g_out2s + (size_t)quarter * (NB * NO * NHW);
    int co_base = cohalf * 64 + q * 16;

    __shared__ float sx[8 * 4 * 66];
    __shared__ float sw[8 * 9 * 64];

    unsigned long long accp[2][8];
#pragma unroll
    for (int r = 0; r < 2; r++)
#pragma unroll
        for (int p = 0; p < 8; p++) accp[r][p] = 0ull;

    for (int ch = 0; ch < 4; ch++) {
        int ci0 = quarter * 32 + ch * 8;
        __syncthreads();
        float4* sw4 = (float4*)sw;
        for (int i = tid; i < 1152; i += 256) {
            int a = i >> 4; int j = i & 15;
            sw4[i] = *(const float4*)(g_wT2 + (size_t)(ci0 * 9 + a) * 128 + cohalf * 64 + j * 4);
        }
        for (int i = tid; i < 8 * 4 * 66; i += 256) {
            int ci = i / 264; int r2 = i - ci * 264; int r = r2 / 66; int wc = r2 - r * 66;
            int hh = h0 - 1 + r; int ww = wc - 1; int c = ci0 + ci;
            float v = 0.f;
            if (hh >= 0 && hh < 64 && ww >= 0 && ww < 64) {
                float raw = g_out1[((size_t)(b * 128 + c) * 64 + hh) * 64 + ww];
                v = fmaxf(0.f, raw * g_scale1[c] + g_shift1[c]);
            }
            sx[i] = v;
        }
        __syncthreads();

        for (int ci = 0; ci < 8; ci++) {
#pragma unroll
            for (int kk = 0; kk < 9; kk++) {
                int ky = kk / 3, kx = kk % 3;
                float x0 = sx[ci * 264 + ky * 66 + w + kx];
                float x1 = sx[ci * 264 + (ky + 1) * 66 + w + kx];
                unsigned long long xb0 = pack2b(x0);
                unsigned long long xb1 = pack2b(x1);
                const ulonglong2* wrow = (const ulonglong2*)&sw[(ci * 9 + kk) * 64 + q * 16];
#pragma unroll
                for (int j4 = 0; j4 < 4; j4++) {
                    ulonglong2 wv = wrow[j4];
                    FFMA2(accp[0][2 * j4],     wv.x, xb0);
                    FFMA2(accp[0][2 * j4 + 1], wv.y, xb0);
                    FFMA2(accp[1][2 * j4],     wv.x, xb1);
                    FFMA2(accp[1][2 * j4 + 1], wv.y, xb1);
                }
            }
        }
    }

#pragma unroll
    for (int r = 0; r < 2; r++) {
        int h = h0 + r;
#pragma unroll
        for (int p = 0; p < 8; p++) {
            float2 f2 = unpack2(accp[r][p]);
            int co = co_base + 2 * p;
            outbuf[((size_t)(b * 128 + co) * 64 + h) * 64 + w]     = f2.x;
            outbuf[((size_t)(b * 128 + co + 1) * 64 + h) * 64 + w] = f2.y;
        }
    }
}

// -------- K5: combine 4 conv2 partials + BN2 stats + fold --------
__global__ __launch_bounds__(256) void k_bn2(const float* __restrict__ gamma,
                                             const float* __restrict__ beta) {
    const size_t N = (size_t)NB * NO * NHW;
    int c = blockIdx.x; int tid = threadIdx.x;
    __shared__ float ssum[256], ssq[256];
    float s = 0.f, sq = 0.f;
    for (int b = 0; b < NB; b++) {
        size_t base = (size_t)(b * 128 + c) * NHW;
        const float4* p0 = (const float4*)(g_out2s + base);
        const float4* p1 = (const float4*)(g_out2s + N + base);
        const float4* p2 = (const float4*)(g_out2s + 2 * N + base);
        const float4* p3 = (const float4*)(g_out2s + 3 * N + base);
        float4* po = (float4*)(g_out2 + base);
        for (int i = tid; i < 1024; i += 256) {
            float4 a = p0[i], bq = p1[i], cq = p2[i], dq = p3[i];
            float4 v = make_float4(a.x + bq.x + cq.x + dq.x, a.y + bq.y + cq.y + dq.y,
                                   a.z + bq.z + cq.z + dq.z, a.w + bq.w + cq.w + dq.w);
            po[i] = v;
            s  += v.x + v.y + v.z + v.w;
            sq += v.x * v.x + v.y * v.y + v.z * v.z + v.w * v.w;
        }
    }
    ssum[tid] = s; ssq[tid] = sq;
    __syncthreads();
    for (int st = 128; st; st >>= 1) {
        if (tid < st) { ssum[tid] += ssum[tid + st]; ssq[tid] += ssq[tid + st]; }
        __syncthreads();
    }
    if (tid == 0) {
        float m  = ssum[0] * (1.f / 16384.f);
        float vv = ssq[0]  * (1.f / 16384.f) - m * m;
        float sc = gamma[c] * rsqrtf(vv + 1e-5f);
        g_scale2[c] = sc;
        g_shift2[c] = beta[c] - m * sc;
    }
}

// -------- K6: final BN2 + ReLU elementwise into d_out --------
__global__ void k_final(float* __restrict__ out) {
    int idx = blockIdx.x * 256 + threadIdx.x;
    const float4* in4 = (const float4*)g_out2;
    float4 v = in4[idx];
    int c = (idx >> 10) & 127;
    float sc = g_scale2[c], sh = g_shift2[c];
    float4 r;
    r.x = fmaxf(0.f, v.x * sc + sh);
    r.y = fmaxf(0.f, v.y * sc + sh);
    r.z = fmaxf(0.f, v.z * sc + sh);
    r.w = fmaxf(0.f, v.w * sc + sh);
    ((float4*)out)[idx] = r;
}

// -------- host launcher (graph-capturable) --------
extern "C" void kernel_launch(void* const* d_in, const int* in_sizes, int n_in,
                              void* d_out, int out_size) {
    const float* input_v = (const float*)d_in[0];
    const float* input_i = (const float*)d_in[1];
    const float* off_w   = (const float*)d_in[2];
    const float* off_b   = (const float*)d_in[3];
    const float* dconv_w = (const float*)d_in[4];
    const float* bn1_g   = (const float*)d_in[5];
    const float* bn1_b   = (const float*)d_in[6];
    const float* conv2_w = (const float*)d_in[7];
    const float* bn2_g   = (const float*)d_in[8];
    const float* bn2_b   = (const float*)d_in[9];
    float* out = (float*)d_out;

    k_prep<<<3238, 256>>>(dconv_w, off_w, conv2_w, input_v, input_i);
    k_offconv<<<512, 256>>>(input_v, input_i);
    k_offpost<<<3456, 256>>>(off_b);
    k_deform<<<1024, 256>>>();
    k_bn1<<<128, 256>>>(bn1_g, bn1_b);
    k_conv2<<<1024, 256>>>();
    k_bn2<<<128, 256>>>(bn2_g, bn2_b);
    k_final<<<2048, 256>>>(out);
}